// round 17
// baseline (speedup 1.0000x reference)
#include <cuda_runtime.h>
#include <cuda_bf16.h>
#include <stdint.h>
#include <math.h>

#define SQ   4096
#define EMB  1152
#define NH   16
#define HD   72
#define HALF 36
#define NSEG 8
#define QKV3 (3*EMB)

#define BQ 64
#define BK 64

#define KSB   88
#define VTSTR 68
#define PQSTR 68

#define OFF_QH  0
#define OFF_QL  (OFF_QH + BQ*KSB*2)
#define OFF_KH  (OFF_QL + BQ*KSB*2)
#define OFF_KL  (OFF_KH + BK*KSB*2)
#define OFF_VT  (OFF_KL + BK*KSB*2)
#define OFF_PQ  (OFF_VT + 80*VTSTR*4)
#define OFF_INT (OFF_PQ + BQ*PQSTR*4)
#define ATTN_SMEM_BYTES (OFF_INT + (64 + 64 + 16) * 4)

static __device__ float g_qkv[(size_t)SQ * QKV3];
static __device__ float g_attn[(size_t)SQ * EMB];

// ---------------------------------------------------------------------------
// helpers
// ---------------------------------------------------------------------------
__device__ __forceinline__ unsigned f2tf32(float x) {
    unsigned r;
    asm("cvt.rna.tf32.f32 %0, %1;" : "=r"(r) : "f"(x));
    return r;
}

__device__ __forceinline__ void mma_tf32(float c[4],
                                         unsigned a0, unsigned a1, unsigned a2, unsigned a3,
                                         unsigned b0, unsigned b1) {
    asm("mma.sync.aligned.m16n8k8.row.col.f32.tf32.tf32.f32 "
        "{%0,%1,%2,%3}, {%4,%5,%6,%7}, {%8,%9}, {%0,%1,%2,%3};"
        : "+f"(c[0]), "+f"(c[1]), "+f"(c[2]), "+f"(c[3])
        : "r"(a0), "r"(a1), "r"(a2), "r"(a3), "r"(b0), "r"(b1));
}

__device__ __forceinline__ void mma_bf16(float c[4],
                                         unsigned a0, unsigned a1, unsigned a2, unsigned a3,
                                         unsigned b0, unsigned b1) {
    asm("mma.sync.aligned.m16n8k16.row.col.f32.bf16.bf16.f32 "
        "{%0,%1,%2,%3}, {%4,%5,%6,%7}, {%8,%9}, {%0,%1,%2,%3};"
        : "+f"(c[0]), "+f"(c[1]), "+f"(c[2]), "+f"(c[3])
        : "r"(a0), "r"(a1), "r"(a2), "r"(a3), "r"(b0), "r"(b1));
}

__device__ __forceinline__ void ldsm_x4(unsigned& r0, unsigned& r1,
                                        unsigned& r2, unsigned& r3, uint32_t addr) {
    asm volatile("ldmatrix.sync.aligned.m8n8.x4.shared.b16 {%0,%1,%2,%3}, [%4];"
                 : "=r"(r0), "=r"(r1), "=r"(r2), "=r"(r3) : "r"(addr));
}
__device__ __forceinline__ void ldsm_x2(unsigned& r0, unsigned& r1, uint32_t addr) {
    asm volatile("ldmatrix.sync.aligned.m8n8.x2.shared.b16 {%0,%1}, [%2];"
                 : "=r"(r0), "=r"(r1) : "r"(addr));
}

__device__ __forceinline__ void bf16_split2(float x, float y, unsigned& hi, unsigned& lo) {
    __nv_bfloat16 hx = __float2bfloat16_rn(x);
    __nv_bfloat16 hy = __float2bfloat16_rn(y);
    __nv_bfloat16 lx = __float2bfloat16_rn(x - __bfloat162float(hx));
    __nv_bfloat16 ly = __float2bfloat16_rn(y - __bfloat162float(hy));
    hi = ((unsigned)__bfloat16_as_ushort(hy) << 16) | __bfloat16_as_ushort(hx);
    lo = ((unsigned)__bfloat16_as_ushort(ly) << 16) | __bfloat16_as_ushort(lx);
}

// ---------------------------------------------------------------------------
// TF32 GEMM: [m][k] packed-tf32 smem (stride 20 floats), ldmatrix fragments,
// double-buffered with register prefetch. C = A[M,K]*B[N,K]^T + bias.
// ---------------------------------------------------------------------------
template<int NN, int KK>
__global__ __launch_bounds__(256)
void gemm_tf32(const float* __restrict__ A, const float* __restrict__ B,
               const float* __restrict__ bias, float* __restrict__ C)
{
    __shared__ float As[2][128 * 20];
    __shared__ float Bs[2][128 * 20];

    const int bm   = blockIdx.y * 128;
    const int bn   = blockIdx.x * 128;
    const int tid  = threadIdx.x;
    const int warp = tid >> 5;
    const int lane = tid & 31;
    const int wm   = warp >> 2;
    const int wn   = warp & 3;
    const int r    = lane >> 2;
    const int c    = lane & 3;

    // staging assignment: tid<128 -> A row (tid), else B row (tid-128)
    const int srow = tid & 127;
    const bool isA = tid < 128;
    const float* gsrc = isA ? (A + (size_t)(bm + srow) * KK)
                            : (B + (size_t)(bn + srow) * KK);
    float* sdst[2] = { (isA ? As[0] : Bs[0]) + srow * 20,
                       (isA ? As[1] : Bs[1]) + srow * 20 };

    // ldmatrix lane addresses (bytes)
    const uint32_t uA[2] = { (uint32_t)__cvta_generic_to_shared(As[0]),
                             (uint32_t)__cvta_generic_to_shared(As[1]) };
    const uint32_t uB[2] = { (uint32_t)__cvta_generic_to_shared(Bs[0]),
                             (uint32_t)__cvta_generic_to_shared(Bs[1]) };
    const int lm16 = lane & 15;
    const uint32_t aA = (uint32_t)((wm * 64 + lm16) * 80 + ((lane >> 4) * 16));
    const uint32_t aB = (uint32_t)((wn * 32 + (lane & 7) + ((lane >> 4) << 3)) * 80
                                   + (((lane >> 3) & 1) * 16));

    float acc[4][4][4];
    #pragma unroll
    for (int mt = 0; mt < 4; mt++)
        #pragma unroll
        for (int nt = 0; nt < 4; nt++)
            #pragma unroll
            for (int i = 0; i < 4; i++) acc[mt][nt][i] = 0.0f;

    float4 pf[4];
    #pragma unroll
    for (int j = 0; j < 4; j++) pf[j] = *(const float4*)(gsrc + j * 4);

    // stage tile 0 -> buffer 0
    #pragma unroll
    for (int j = 0; j < 4; j++) {
        uint4 o;
        o.x = f2tf32(pf[j].x); o.y = f2tf32(pf[j].y);
        o.z = f2tf32(pf[j].z); o.w = f2tf32(pf[j].w);
        *(uint4*)(sdst[0] + j * 4) = o;
    }
    __syncthreads();

    const int NKT = KK / 16;
    for (int kt = 0; kt < NKT; kt++) {
        const int cur = kt & 1;
        if (kt + 1 < NKT) {
            const int k0 = (kt + 1) * 16;
            #pragma unroll
            for (int j = 0; j < 4; j++) pf[j] = *(const float4*)(gsrc + k0 + j * 4);
        }

        const uint32_t ua = uA[cur], ub = uB[cur];
        #pragma unroll
        for (int kc = 0; kc < 16; kc += 8) {
            unsigned af[4][4], bf[4][2];
            #pragma unroll
            for (int mt = 0; mt < 4; mt++)
                ldsm_x4(af[mt][0], af[mt][1], af[mt][2], af[mt][3],
                        ua + aA + (uint32_t)(mt * 1280 + kc * 4));
            #pragma unroll
            for (int np = 0; np < 2; np++)
                ldsm_x4(bf[2*np][0], bf[2*np][1], bf[2*np+1][0], bf[2*np+1][1],
                        ub + aB + (uint32_t)(np * 1280 + kc * 4));
            #pragma unroll
            for (int mt = 0; mt < 4; mt++)
                #pragma unroll
                for (int nt = 0; nt < 4; nt++)
                    mma_tf32(acc[mt][nt], af[mt][0], af[mt][1], af[mt][2], af[mt][3],
                             bf[nt][0], bf[nt][1]);
        }

        if (kt + 1 < NKT) {
            const int nxt = cur ^ 1;
            #pragma unroll
            for (int j = 0; j < 4; j++) {
                uint4 o;
                o.x = f2tf32(pf[j].x); o.y = f2tf32(pf[j].y);
                o.z = f2tf32(pf[j].z); o.w = f2tf32(pf[j].w);
                *(uint4*)(sdst[nxt] + j * 4) = o;
            }
            __syncthreads();
        }
    }

    #pragma unroll
    for (int nt = 0; nt < 4; nt++) {
        const int col = bn + wn * 32 + nt * 8 + 2 * c;
        const float2 bb = *(const float2*)(bias + col);
        #pragma unroll
        for (int mt = 0; mt < 4; mt++) {
            const int row0 = bm + wm * 64 + mt * 16 + r;
            float2 o0 = make_float2(acc[mt][nt][0] + bb.x, acc[mt][nt][1] + bb.y);
            float2 o1 = make_float2(acc[mt][nt][2] + bb.x, acc[mt][nt][3] + bb.y);
            *(float2*)&C[(size_t)row0 * NN + col]       = o0;
            *(float2*)&C[(size_t)(row0 + 8) * NN + col] = o1;
        }
    }
}

// ---------------------------------------------------------------------------
// RoPE in-place on q,k halves of g_qkv.
// ---------------------------------------------------------------------------
__global__ __launch_bounds__(256)
void rope_kernel(const float* __restrict__ cosT, const float* __restrict__ sinT)
{
    int idx = blockIdx.x * blockDim.x + threadIdx.x;
    const int total = SQ * 2 * NH * HALF;
    if (idx >= total) return;
    int d  = idx % HALF;
    int h  = (idx / HALF) % NH;
    int qk = (idx / (HALF * NH)) & 1;
    int s  = idx / (HALF * NH * 2);

    float* base = g_qkv + (size_t)s * QKV3 + qk * EMB + h * HD;
    float x1 = base[d];
    float x2 = base[d + HALF];
    float c  = cosT[(size_t)s * HD + d];
    float sn = sinT[(size_t)s * HD + d];
    base[d]        = x1 * c - x2 * sn;
    base[d + HALF] = x2 * c + x1 * sn;
}

// ---------------------------------------------------------------------------
// Attention (R14, unchanged): 3xBF16 S, tf32 PV, ldmatrix, 2 CTAs/SM.
// ---------------------------------------------------------------------------
__global__ __launch_bounds__(256, 2)
void attn_kernel(const float* __restrict__ qkv, const int* __restrict__ cu,
                 float* __restrict__ out)
{
    extern __shared__ char smb[];
    unsigned* QhW = (unsigned*)(smb + OFF_QH);
    unsigned* QlW = (unsigned*)(smb + OFF_QL);
    unsigned* KhW = (unsigned*)(smb + OFF_KH);
    unsigned* KlW = (unsigned*)(smb + OFF_KL);
    float*    Vt  = (float*)(smb + OFF_VT);
    float*    Pq  = (float*)(smb + OFF_PQ);
    int* segq = (int*)(smb + OFF_INT);
    int* segk = segq + 64;
    int* cus  = segk + 64;

    const int tid  = threadIdx.x;
    const int lane = tid & 31;
    const int warp = tid >> 5;
    const int r    = lane >> 2;
    const int cq   = lane & 3;
    const int nb   = warp * 8;
    const int h    = blockIdx.y;
    const int q0   = blockIdx.x * BQ;

    const uint32_t uBase = (uint32_t)__cvta_generic_to_shared(smb);
    const uint32_t uQh = uBase + OFF_QH;
    const uint32_t uQl = uBase + OFF_QL;
    const uint32_t uKh = uBase + OFF_KH;
    const uint32_t uKl = uBase + OFF_KL;
    const uint32_t uVt = uBase + OFF_VT;
    const uint32_t uPq = uBase + OFF_PQ;

    const int lm16  = lane & 15;
    const int lsel4 = (lane >> 4) & 1;
    const int lm8   = lane & 7;
    const int lsel2 = (lane >> 3) & 1;
    const uint32_t aQb = (uint32_t)((nb + lm8) * KSB * 2 + lsel2 * 16);
    const uint32_t aKb = (uint32_t)(lm16 * KSB * 2 + lsel4 * 16);
    const uint32_t aV = uVt + (uint32_t)(lm16 * VTSTR + lsel4 * 4) * 4;
    const uint32_t aP = uPq + (uint32_t)((nb + lm8) * PQSTR + lsel2 * 4) * 4;

    if (tid <= NSEG) cus[tid] = cu[tid];
    __syncthreads();

    if (tid < BQ) {
        int p = q0 + tid;
        int s = 0;
        #pragma unroll
        for (int i = 1; i <= NSEG; i++) s += (p >= cus[i]);
        segq[tid] = s;
    }
    #pragma unroll
    for (int it = 0; it < 9; it++) {
        int idx = tid + it * 256;
        int row = idx / 36, dp = (idx % 36) * 2;
        float2 q2 = *(const float2*)(qkv + (size_t)(q0 + row) * QKV3 + h * HD + dp);
        unsigned hi, lo;
        bf16_split2(q2.x, q2.y, hi, lo);
        QhW[(row * KSB + dp) >> 1] = hi;
        QlW[(row * KSB + dp) >> 1] = lo;
    }
    for (int i = tid; i < 64 * 8; i += 256) {
        int row = i >> 3, w = i & 7;
        int wi = (row * KSB + 72) / 2 + w;
        QhW[wi] = 0; QlW[wi] = 0; KhW[wi] = 0; KlW[wi] = 0;
    }
    for (int i = tid; i < 8 * 64; i += 256)
        Vt[(HD + (i >> 6)) * VTSTR + (i & 63)] = 0.0f;
    __syncthreads();

    const int sq0 = segq[nb + 2 * cq];
    const int sq1 = segq[nb + 2 * cq + 1];
    const int k_lo = cus[segq[0]];
    const int k_hi = cus[segq[BQ - 1] + 1];

    float m[2]  = {-1e30f, -1e30f};
    float l[2]  = {0.0f, 0.0f};
    float oa[5][4];
    #pragma unroll
    for (int mt = 0; mt < 5; mt++)
        #pragma unroll
        for (int i = 0; i < 4; i++) oa[mt][i] = 0.0f;

    const float scale = 0.11785113019775793f;

    for (int kk0 = k_lo; kk0 < k_hi; kk0 += BK) {
        #pragma unroll
        for (int it = 0; it < 9; it++) {
            int idx = tid + it * 256;
            int ky = idx / 36, dp = (idx % 36) * 2;
            int key = kk0 + ky;
            float2 k2 = make_float2(0.0f, 0.0f), v2 = make_float2(0.0f, 0.0f);
            if (key < k_hi) {
                const float* rowp = qkv + (size_t)key * QKV3 + h * HD + dp;
                k2 = *(const float2*)(rowp + EMB);
                v2 = *(const float2*)(rowp + 2 * EMB);
            }
            unsigned hi, lo;
            bf16_split2(k2.x, k2.y, hi, lo);
            KhW[(ky * KSB + dp) >> 1] = hi;
            KlW[(ky * KSB + dp) >> 1] = lo;
            Vt[dp * VTSTR + ky]       = __uint_as_float(f2tf32(v2.x));
            Vt[(dp + 1) * VTSTR + ky] = __uint_as_float(f2tf32(v2.y));
        }
        if (tid < BK) {
            int key = kk0 + tid;
            int s = -1;
            if (key < k_hi) {
                s = 0;
                #pragma unroll
                for (int i = 1; i <= NSEG; i++) s += (key >= cus[i]);
            }
            segk[tid] = s;
        }
        __syncthreads();

        float sf[4][4];
        #pragma unroll
        for (int mt = 0; mt < 4; mt++)
            #pragma unroll
            for (int i = 0; i < 4; i++) sf[mt][i] = 0.0f;

        #pragma unroll
        for (int c5 = 0; c5 < 5; c5++) {
            unsigned bh0, bh1, bl0, bl1;
            ldsm_x2(bh0, bh1, uQh + aQb + c5 * 32);
            ldsm_x2(bl0, bl1, uQl + aQb + c5 * 32);
            #pragma unroll
            for (int mt = 0; mt < 4; mt++) {
                const uint32_t koff = aKb + (uint32_t)(mt * 16 * KSB * 2 + c5 * 32);
                unsigned ah0, ah1, ah2, ah3, al0, al1, al2, al3;
                ldsm_x4(ah0, ah1, ah2, ah3, uKh + koff);
                ldsm_x4(al0, al1, al2, al3, uKl + koff);
                mma_bf16(sf[mt], ah0, ah1, ah2, ah3, bh0, bh1);
                mma_bf16(sf[mt], ah0, ah1, ah2, ah3, bl0, bl1);
                mma_bf16(sf[mt], al0, al1, al2, al3, bh0, bh1);
            }
        }

        int skr[4][2];
        #pragma unroll
        for (int mt = 0; mt < 4; mt++) {
            skr[mt][0] = segk[mt * 16 + r];
            skr[mt][1] = segk[mt * 16 + r + 8];
        }

        const int sqv[2] = {sq0, sq1};
        #pragma unroll
        for (int qq = 0; qq < 2; qq++) {
            float mx = -1e30f;
            #pragma unroll
            for (int mt = 0; mt < 4; mt++) {
                float v0 = (skr[mt][0] == sqv[qq]) ? sf[mt][qq] * scale     : -1e30f;
                float v1 = (skr[mt][1] == sqv[qq]) ? sf[mt][qq + 2] * scale : -1e30f;
                sf[mt][qq]     = v0;
                sf[mt][qq + 2] = v1;
                mx = fmaxf(mx, fmaxf(v0, v1));
            }
            mx = fmaxf(mx, __shfl_xor_sync(0xffffffffu, mx, 4));
            mx = fmaxf(mx, __shfl_xor_sync(0xffffffffu, mx, 8));
            mx = fmaxf(mx, __shfl_xor_sync(0xffffffffu, mx, 16));

            float mn  = fmaxf(m[qq], mx);
            float fac = __expf(m[qq] - mn);
            m[qq] = mn;

            float sum = 0.0f;
            #pragma unroll
            for (int mt = 0; mt < 4; mt++) {
                float p0 = (sf[mt][qq]     > -1e29f) ? __expf(sf[mt][qq]     - mn) : 0.0f;
                float p1 = (sf[mt][qq + 2] > -1e29f) ? __expf(sf[mt][qq + 2] - mn) : 0.0f;
                sf[mt][qq]     = p0;
                sf[mt][qq + 2] = p1;
                sum += p0 + p1;
            }
            sum += __shfl_xor_sync(0xffffffffu, sum, 4);
            sum += __shfl_xor_sync(0xffffffffu, sum, 8);
            sum += __shfl_xor_sync(0xffffffffu, sum, 16);
            l[qq] = l[qq] * fac + sum;

            #pragma unroll
            for (int mt = 0; mt < 5; mt++) {
                oa[mt][qq]     *= fac;
                oa[mt][qq + 2] *= fac;
            }
        }

        #pragma unroll
        for (int mt = 0; mt < 4; mt++) {
            #pragma unroll
            for (int half = 0; half < 2; half++) {
                const int krow = mt * 16 + r + half * 8;
                unsigned h0 = f2tf32(sf[mt][half * 2]);
                unsigned h1 = f2tf32(sf[mt][half * 2 + 1]);
                Pq[(nb + 2 * cq)     * PQSTR + krow] = __uint_as_float(h0);
                Pq[(nb + 2 * cq + 1) * PQSTR + krow] = __uint_as_float(h1);
            }
        }
        __syncthreads();

        #pragma unroll
        for (int k0 = 0; k0 < BK; k0 += 8) {
            unsigned b0, b1;
            ldsm_x2(b0, b1, aP + k0 * 4);
            #pragma unroll
            for (int mt = 0; mt < 5; mt++) {
                unsigned a0, a1, a2, a3;
                ldsm_x4(a0, a1, a2, a3, aV + (uint32_t)(mt * 16 * VTSTR + k0) * 4);
                mma_tf32(oa[mt], a0, a1, a2, a3, b0, b1);
            }
        }
        __syncthreads();
    }

    const float inv0 = 1.0f / l[0];
    const float inv1 = 1.0f / l[1];
    const size_t qa = (size_t)(q0 + nb + 2 * cq);
    const size_t qb = qa + 1;
    #pragma unroll
    for (int mt = 0; mt < 5; mt++) {
        int d0 = mt * 16 + r;
        int d1 = d0 + 8;
        if (d0 < HD) {
            out[qa * EMB + h * HD + d0] = oa[mt][0] * inv0;
            out[qb * EMB + h * HD + d0] = oa[mt][1] * inv1;
        }
        if (d1 < HD) {
            out[qa * EMB + h * HD + d1] = oa[mt][2] * inv0;
            out[qb * EMB + h * HD + d1] = oa[mt][3] * inv1;
        }
    }
}

// ---------------------------------------------------------------------------
extern "C" void kernel_launch(void* const* d_in, const int* in_sizes, int n_in,
                              void* d_out, int out_size)
{
    const float* hidden = (const float*)d_in[0];
    const int*   cu     = (const int*)  d_in[1];
    const float* cosT   = (const float*)d_in[2];
    const float* sinT   = (const float*)d_in[3];
    const float* w_qkv  = (const float*)d_in[4];
    const float* b_qkv  = (const float*)d_in[5];
    const float* w_out  = (const float*)d_in[6];
    const float* b_out  = (const float*)d_in[7];
    float* out = (float*)d_out;

    void* p_qkv = nullptr;
    void* p_attn = nullptr;
    cudaGetSymbolAddress(&p_qkv, g_qkv);
    cudaGetSymbolAddress(&p_attn, g_attn);
    float* qkv  = (float*)p_qkv;
    float* attn = (float*)p_attn;

    // 1) QKV projection (tf32, ldmatrix fragment path)
    dim3 g1(QKV3 / 128, SQ / 128);
    gemm_tf32<QKV3, EMB><<<g1, 256>>>(hidden, w_qkv, b_qkv, qkv);

    // 2) RoPE in place
    const int total = SQ * 2 * NH * HALF;
    rope_kernel<<<(total + 255) / 256, 256>>>(cosT, sinT);

    // 3) attention (3xBF16 S, tf32 PV, 2 CTAs/SM)
    cudaFuncSetAttribute(attn_kernel, cudaFuncAttributeMaxDynamicSharedMemorySize,
                         ATTN_SMEM_BYTES);
    attn_kernel<<<dim3(SQ / BQ, NH), 256, ATTN_SMEM_BYTES>>>(qkv, cu, attn);

    // 4) output projection
    dim3 g2(EMB / 128, SQ / 128);
    gemm_tf32<EMB, EMB><<<g2, 256>>>(attn, w_out, b_out, out);
}